// round 5
// baseline (speedup 1.0000x reference)
#include <cuda_runtime.h>

#define BB 32
#define SS 2048
#define NROWS (BB * SS)
#define NSPLIT 2

// Scratch: __device__ globals (no allocation allowed in kernel_launch).
__device__ float4 g_Q[NROWS];            // pre-scaled by 0.5*log2(e)
// Pair-packed layouts: for key pair p (rows 2p, 2p+1):
//   g_Kp[2p]   = (k0.x, k1.x, k0.y, k1.y)
//   g_Kp[2p+1] = (k0.z, k1.z, k0.w, k1.w)
__device__ float4 g_Kp[NROWS];
__device__ float4 g_Vp[NROWS];
__device__ float4 g_pnum[NSPLIT * NROWS];  // partial sum(e*V)
__device__ float  g_pden[NSPLIT * NROWS];  // partial sum(e)

typedef unsigned long long ull;

// ---------------------------------------------------------------------------
// Packed f32x2 helpers (sm_103a FFMA2 path — ptxas won't auto-fuse from C++)
// ---------------------------------------------------------------------------
__device__ __forceinline__ ull pack2(float lo, float hi) {
    ull r; asm("mov.b64 %0, {%1, %2};" : "=l"(r) : "f"(lo), "f"(hi)); return r;
}
__device__ __forceinline__ void unpack2(ull v, float& lo, float& hi) {
    asm("mov.b64 {%0, %1}, %2;" : "=f"(lo), "=f"(hi) : "l"(v));
}
__device__ __forceinline__ ull fma2(ull a, ull b, ull c) {
    ull d; asm("fma.rn.f32x2 %0, %1, %2, %3;" : "=l"(d) : "l"(a), "l"(b), "l"(c)); return d;
}
__device__ __forceinline__ ull mul2(ull a, ull b) {
    ull d; asm("mul.rn.f32x2 %0, %1, %2;" : "=l"(d) : "l"(a), "l"(b)); return d;
}
__device__ __forceinline__ ull add2(ull a, ull b) {
    ull d; asm("add.rn.f32x2 %0, %1, %2;" : "=l"(d) : "l"(a), "l"(b)); return d;
}
__device__ __forceinline__ float fast_exp2(float x) {
    float y; asm("ex2.approx.ftz.f32 %0, %1;" : "=f"(y) : "f"(x)); return y;
}

// ---------------------------------------------------------------------------
// 16-dim statevector circuit: qubit q lives at bit (3-q). Fully unrolled;
// CNOTs are free register renames.
// ---------------------------------------------------------------------------
template <int Q>
__device__ __forceinline__ void rx_gate(float sr[16], float si[16], float c, float sn) {
    const int m = 1 << (3 - Q);
#pragma unroll
    for (int i = 0; i < 16; i++) {
        if (!(i & m)) {
            const int j = i | m;
            float a0r = sr[i], a0i = si[i];
            float a1r = sr[j], a1i = si[j];
            sr[i] = c * a0r + sn * a1i;
            si[i] = c * a0i - sn * a1r;
            sr[j] = c * a1r + sn * a0i;
            si[j] = c * a1i - sn * a0r;
        }
    }
}

template <int Q>
__device__ __forceinline__ void cnot_gate(float sr[16], float si[16]) {
    const int cm = 1 << (3 - Q);
    const int tm = 1 << (3 - ((Q + 1) & 3));
#pragma unroll
    for (int i = 0; i < 16; i++) {
        if ((i & cm) && !(i & tm)) {
            const int j = i | tm;
            float t;
            t = sr[i]; sr[i] = sr[j]; sr[j] = t;
            t = si[i]; si[i] = si[j]; si[j] = t;
        }
    }
}

__device__ __forceinline__ float4 layer_and_measure(
    const float er[16], const float ei[16],
    const float wc[4], const float ws[4])
{
    float sr[16], si[16];
#pragma unroll
    for (int i = 0; i < 16; i++) { sr[i] = er[i]; si[i] = ei[i]; }

    rx_gate<0>(sr, si, wc[0], ws[0]);
    rx_gate<1>(sr, si, wc[1], ws[1]);
    rx_gate<2>(sr, si, wc[2], ws[2]);
    rx_gate<3>(sr, si, wc[3], ws[3]);
    cnot_gate<0>(sr, si);
    cnot_gate<1>(sr, si);
    cnot_gate<2>(sr, si);
    cnot_gate<3>(sr, si);

    float e0 = 0.f, e1 = 0.f, e2 = 0.f, e3 = 0.f;
#pragma unroll
    for (int i = 0; i < 16; i++) {
        float p = sr[i] * sr[i] + si[i] * si[i];
        e0 += (i & 8) ? -p : p;
        e1 += (i & 4) ? -p : p;
        e2 += (i & 2) ? -p : p;
        e3 += (i & 1) ? -p : p;
    }
    return make_float4(e0, e1, e2, e3);
}

// MUFU-based sincos: half-angles here are small (x ~ N(0,1)*0.5, ctx in
// [-0.5, 0.5]) so __sincosf's accuracy (~2^-21 abs) is far inside the 1e-3
// tolerance.
__device__ __forceinline__ void embed(float4 ang, float er[16], float ei[16]) {
#pragma unroll
    for (int i = 0; i < 16; i++) { er[i] = 0.f; ei[i] = 0.f; }
    er[0] = 1.f;
    float c, sn;
    __sincosf(ang.x * 0.5f, &sn, &c); rx_gate<0>(er, ei, c, sn);
    __sincosf(ang.y * 0.5f, &sn, &c); rx_gate<1>(er, ei, c, sn);
    __sincosf(ang.z * 0.5f, &sn, &c); rx_gate<2>(er, ei, c, sn);
    __sincosf(ang.w * 0.5f, &sn, &c); rx_gate<3>(er, ei, c, sn);
}

// Weights: uniform across threads; keep precise sincosf (range [0, pi]).
__device__ __forceinline__ void load_w(const float* __restrict__ w, float wc[4], float ws[4]) {
#pragma unroll
    for (int i = 0; i < 4; i++) sincosf(w[i] * 0.5f, &ws[i], &wc[i]);
}

// ---------------------------------------------------------------------------
// Kernel 1: x -> Q (row layout, pre-scaled), K, V (pair-packed layout).
// ---------------------------------------------------------------------------
__global__ void qkv_kernel(const float4* __restrict__ x,
                           const float* __restrict__ wQ,
                           const float* __restrict__ wK,
                           const float* __restrict__ wV)
{
    int idx = blockIdx.x * blockDim.x + threadIdx.x;
    if (idx >= NROWS) return;

    float er[16], ei[16];
    embed(x[idx], er, ei);

    float wc[4], ws[4];
    const float scale = 0.5f * 1.4426950408889634f;  // 1/sqrt(E) * log2(e)
    load_w(wQ, wc, ws);
    {
        float4 qv = layer_and_measure(er, ei, wc, ws);
        qv.x *= scale; qv.y *= scale; qv.z *= scale; qv.w *= scale;
        g_Q[idx] = qv;
    }

    const int p = idx >> 1;
    const int h = idx & 1;
    float* gk = (float*)g_Kp;
    float* gv = (float*)g_Vp;

    load_w(wK, wc, ws);
    {
        float4 k = layer_and_measure(er, ei, wc, ws);
        gk[p * 8 + 0 + h] = k.x;
        gk[p * 8 + 2 + h] = k.y;
        gk[p * 8 + 4 + h] = k.z;
        gk[p * 8 + 6 + h] = k.w;
    }
    load_w(wV, wc, ws);
    {
        float4 v = layer_and_measure(er, ei, wc, ws);
        gv[p * 8 + 0 + h] = v.x;
        gv[p * 8 + 2 + h] = v.y;
        gv[p * 8 + 4 + h] = v.z;
        gv[p * 8 + 6 + h] = v.w;
    }
}

// ---------------------------------------------------------------------------
// Kernel 2: split-K flash attention partials.
// QPT=2 queries/thread, 2 keys per packed f32x2 lane-pair, split-K=2.
// Each block: 256 queries x 1024 keys; K/V half staged once in SMEM.
// Scores in [-2,2] -> raw exp2 softmax (no max subtraction), exact to combine
// across splits by summation.
// ---------------------------------------------------------------------------
#define ATTN_TPB   128
#define KEYS_HALF  (SS / NSPLIT)        // 1024 keys = 1024 packed float4

__global__ void __launch_bounds__(ATTN_TPB)
attn_kernel()
{
    __shared__ float4 sK[KEYS_HALF];
    __shared__ float4 sV[KEYS_HALF];

    const int b     = blockIdx.y;
    const int split = blockIdx.z;
    const int t     = threadIdx.x;
    const int qrow  = b * SS + blockIdx.x * (ATTN_TPB * 2) + t;

    // Stage this split's K/V half.
#pragma unroll
    for (int i = t; i < KEYS_HALF; i += ATTN_TPB) {
        sK[i] = g_Kp[b * SS + split * KEYS_HALF + i];
        sV[i] = g_Vp[b * SS + split * KEYS_HALF + i];
    }

    float4 qa = g_Q[qrow];
    float4 qb = g_Q[qrow + ATTN_TPB];

    const ull qa_x = pack2(qa.x, qa.x), qa_y = pack2(qa.y, qa.y);
    const ull qa_z = pack2(qa.z, qa.z), qa_w = pack2(qa.w, qa.w);
    const ull qb_x = pack2(qb.x, qb.x), qb_y = pack2(qb.y, qb.y);
    const ull qb_z = pack2(qb.z, qb.z), qb_w = pack2(qb.w, qb.w);

    ull den_a = 0, den_b = 0;
    ull aa0 = 0, aa1 = 0, aa2 = 0, aa3 = 0;
    ull ab0 = 0, ab1 = 0, ab2 = 0, ab3 = 0;

    __syncthreads();

    const ulonglong2* kk = (const ulonglong2*)sK;
    const ulonglong2* vv = (const ulonglong2*)sV;

#pragma unroll 4
    for (int p = 0; p < KEYS_HALF / 2; p++) {
        ulonglong2 ka = kk[2 * p];      // (kx pair, ky pair)
        ulonglong2 kb = kk[2 * p + 1];  // (kz pair, kw pair)

        ull sa = fma2(qa_x, ka.x, fma2(qa_y, ka.y, fma2(qa_z, kb.x, mul2(qa_w, kb.y))));
        ull sb = fma2(qb_x, ka.x, fma2(qb_y, ka.y, fma2(qb_z, kb.x, mul2(qb_w, kb.y))));

        float s0, s1;
        unpack2(sa, s0, s1);
        ull ea = pack2(fast_exp2(s0), fast_exp2(s1));
        unpack2(sb, s0, s1);
        ull eb = pack2(fast_exp2(s0), fast_exp2(s1));

        den_a = add2(den_a, ea);
        den_b = add2(den_b, eb);

        ulonglong2 va = vv[2 * p];
        ulonglong2 vb = vv[2 * p + 1];

        aa0 = fma2(ea, va.x, aa0);
        aa1 = fma2(ea, va.y, aa1);
        aa2 = fma2(ea, vb.x, aa2);
        aa3 = fma2(ea, vb.y, aa3);
        ab0 = fma2(eb, va.x, ab0);
        ab1 = fma2(eb, va.y, ab1);
        ab2 = fma2(eb, vb.x, ab2);
        ab3 = fma2(eb, vb.y, ab3);
    }

    const int base = split * NROWS;
    {
        float d0, d1, u0, u1;
        float4 num;
        unpack2(aa0, u0, u1); num.x = u0 + u1;
        unpack2(aa1, u0, u1); num.y = u0 + u1;
        unpack2(aa2, u0, u1); num.z = u0 + u1;
        unpack2(aa3, u0, u1); num.w = u0 + u1;
        unpack2(den_a, d0, d1);
        g_pnum[base + qrow] = num;
        g_pden[base + qrow] = d0 + d1;
    }
    {
        float d0, d1, u0, u1;
        float4 num;
        unpack2(ab0, u0, u1); num.x = u0 + u1;
        unpack2(ab1, u0, u1); num.y = u0 + u1;
        unpack2(ab2, u0, u1); num.z = u0 + u1;
        unpack2(ab3, u0, u1); num.w = u0 + u1;
        unpack2(den_b, d0, d1);
        g_pnum[base + qrow + ATTN_TPB] = num;
        g_pden[base + qrow + ATTN_TPB] = d0 + d1;
    }
}

// ---------------------------------------------------------------------------
// Kernel 3: combine split partials -> ctx -> circuit(weights_C) -> out
// ---------------------------------------------------------------------------
__global__ void out_kernel(const float* __restrict__ wC, float4* __restrict__ out)
{
    int idx = blockIdx.x * blockDim.x + threadIdx.x;
    if (idx >= NROWS) return;

    float4 n0 = g_pnum[idx];
    float4 n1 = g_pnum[NROWS + idx];
    float  d  = g_pden[idx] + g_pden[NROWS + idx];
    float inv = __fdividef(1.f, d);
    float4 ctx = make_float4((n0.x + n1.x) * inv, (n0.y + n1.y) * inv,
                             (n0.z + n1.z) * inv, (n0.w + n1.w) * inv);

    float er[16], ei[16];
    embed(ctx, er, ei);

    float wc[4], ws[4];
    load_w(wC, wc, ws);
    out[idx] = layer_and_measure(er, ei, wc, ws);
}

// ---------------------------------------------------------------------------

extern "C" void kernel_launch(void* const* d_in, const int* in_sizes, int n_in,
                              void* d_out, int out_size)
{
    const float4* x  = (const float4*)d_in[0];
    const float*  wQ = (const float*)d_in[1];
    const float*  wK = (const float*)d_in[2];
    const float*  wV = (const float*)d_in[3];
    const float*  wC = (const float*)d_in[4];

    qkv_kernel<<<NROWS / 128, 128>>>(x, wQ, wK, wV);

    dim3 grid(SS / (ATTN_TPB * 2), BB, NSPLIT);
    attn_kernel<<<grid, ATTN_TPB>>>();

    out_kernel<<<NROWS / 128, 128>>>(wC, (float4*)d_out);
}

// round 6
// speedup vs baseline: 1.5663x; 1.5663x over previous
#include <cuda_runtime.h>

#define BB 32
#define SS 2048
#define NROWS (BB * SS)
#define NSPLIT 2

// Scratch: __device__ globals (no allocation allowed in kernel_launch).
__device__ float4 g_Q[NROWS];            // pre-scaled by 0.5*log2(e)
// Pair-packed layouts: for key pair p (rows 2p, 2p+1):
//   g_Kp[2p]   = (k0.x, k1.x, k0.y, k1.y)
//   g_Kp[2p+1] = (k0.z, k1.z, k0.w, k1.w)
__device__ float4 g_Kp[NROWS];
__device__ float4 g_Vp[NROWS];
__device__ float4 g_pnum[NSPLIT * NROWS];  // partial sum(e*V)
__device__ float  g_pden[NSPLIT * NROWS];  // partial sum(e)

typedef unsigned long long ull;

// ---------------------------------------------------------------------------
// Packed f32x2 helpers (sm_103a FFMA2 path — ptxas won't auto-fuse from C++)
// ---------------------------------------------------------------------------
__device__ __forceinline__ ull pack2(float lo, float hi) {
    ull r; asm("mov.b64 %0, {%1, %2};" : "=l"(r) : "f"(lo), "f"(hi)); return r;
}
__device__ __forceinline__ void unpack2(ull v, float& lo, float& hi) {
    asm("mov.b64 {%0, %1}, %2;" : "=f"(lo), "=f"(hi) : "l"(v));
}
__device__ __forceinline__ ull fma2(ull a, ull b, ull c) {
    ull d; asm("fma.rn.f32x2 %0, %1, %2, %3;" : "=l"(d) : "l"(a), "l"(b), "l"(c)); return d;
}
__device__ __forceinline__ ull mul2(ull a, ull b) {
    ull d; asm("mul.rn.f32x2 %0, %1, %2;" : "=l"(d) : "l"(a), "l"(b)); return d;
}
__device__ __forceinline__ ull add2(ull a, ull b) {
    ull d; asm("add.rn.f32x2 %0, %1, %2;" : "=l"(d) : "l"(a), "l"(b)); return d;
}
__device__ __forceinline__ float fast_exp2(float x) {
    float y; asm("ex2.approx.ftz.f32 %0, %1;" : "=f"(y) : "f"(x)); return y;
}

// ---------------------------------------------------------------------------
// 16-dim statevector circuit: qubit q lives at bit (3-q). Fully unrolled;
// CNOTs are free register renames.
// ---------------------------------------------------------------------------
template <int Q>
__device__ __forceinline__ void rx_gate(float sr[16], float si[16], float c, float sn) {
    const int m = 1 << (3 - Q);
#pragma unroll
    for (int i = 0; i < 16; i++) {
        if (!(i & m)) {
            const int j = i | m;
            float a0r = sr[i], a0i = si[i];
            float a1r = sr[j], a1i = si[j];
            sr[i] = c * a0r + sn * a1i;
            si[i] = c * a0i - sn * a1r;
            sr[j] = c * a1r + sn * a0i;
            si[j] = c * a1i - sn * a0r;
        }
    }
}

template <int Q>
__device__ __forceinline__ void cnot_gate(float sr[16], float si[16]) {
    const int cm = 1 << (3 - Q);
    const int tm = 1 << (3 - ((Q + 1) & 3));
#pragma unroll
    for (int i = 0; i < 16; i++) {
        if ((i & cm) && !(i & tm)) {
            const int j = i | tm;
            float t;
            t = sr[i]; sr[i] = sr[j]; sr[j] = t;
            t = si[i]; si[i] = si[j]; si[j] = t;
        }
    }
}

__device__ __forceinline__ float4 layer_and_measure(
    const float er[16], const float ei[16],
    const float wc[4], const float ws[4])
{
    float sr[16], si[16];
#pragma unroll
    for (int i = 0; i < 16; i++) { sr[i] = er[i]; si[i] = ei[i]; }

    rx_gate<0>(sr, si, wc[0], ws[0]);
    rx_gate<1>(sr, si, wc[1], ws[1]);
    rx_gate<2>(sr, si, wc[2], ws[2]);
    rx_gate<3>(sr, si, wc[3], ws[3]);
    cnot_gate<0>(sr, si);
    cnot_gate<1>(sr, si);
    cnot_gate<2>(sr, si);
    cnot_gate<3>(sr, si);

    float e0 = 0.f, e1 = 0.f, e2 = 0.f, e3 = 0.f;
#pragma unroll
    for (int i = 0; i < 16; i++) {
        float p = sr[i] * sr[i] + si[i] * si[i];
        e0 += (i & 8) ? -p : p;
        e1 += (i & 4) ? -p : p;
        e2 += (i & 2) ? -p : p;
        e3 += (i & 1) ? -p : p;
    }
    return make_float4(e0, e1, e2, e3);
}

// MUFU-based sincos: half-angles are small (x ~ N(0,1)*0.5, ctx in [-0.5,0.5])
// so __sincosf accuracy is far inside the 1e-3 tolerance.
__device__ __forceinline__ void embed(float4 ang, float er[16], float ei[16]) {
#pragma unroll
    for (int i = 0; i < 16; i++) { er[i] = 0.f; ei[i] = 0.f; }
    er[0] = 1.f;
    float c, sn;
    __sincosf(ang.x * 0.5f, &sn, &c); rx_gate<0>(er, ei, c, sn);
    __sincosf(ang.y * 0.5f, &sn, &c); rx_gate<1>(er, ei, c, sn);
    __sincosf(ang.z * 0.5f, &sn, &c); rx_gate<2>(er, ei, c, sn);
    __sincosf(ang.w * 0.5f, &sn, &c); rx_gate<3>(er, ei, c, sn);
}

// Weights: uniform across threads; keep precise sincosf (range [0, pi]).
__device__ __forceinline__ void load_w(const float* __restrict__ w, float wc[4], float ws[4]) {
#pragma unroll
    for (int i = 0; i < 4; i++) sincosf(w[i] * 0.5f, &ws[i], &wc[i]);
}

// ---------------------------------------------------------------------------
// Kernel 1: x -> Q (row layout, pre-scaled), K, V (pair-packed layout).
// ---------------------------------------------------------------------------
__global__ void qkv_kernel(const float4* __restrict__ x,
                           const float* __restrict__ wQ,
                           const float* __restrict__ wK,
                           const float* __restrict__ wV)
{
    int idx = blockIdx.x * blockDim.x + threadIdx.x;
    if (idx >= NROWS) return;

    float er[16], ei[16];
    embed(x[idx], er, ei);

    float wc[4], ws[4];
    const float scale = 0.5f * 1.4426950408889634f;  // 1/sqrt(E) * log2(e)
    load_w(wQ, wc, ws);
    {
        float4 qv = layer_and_measure(er, ei, wc, ws);
        qv.x *= scale; qv.y *= scale; qv.z *= scale; qv.w *= scale;
        g_Q[idx] = qv;
    }

    const int p = idx >> 1;
    const int h = idx & 1;
    float* gk = (float*)g_Kp;
    float* gv = (float*)g_Vp;

    load_w(wK, wc, ws);
    {
        float4 k = layer_and_measure(er, ei, wc, ws);
        gk[p * 8 + 0 + h] = k.x;
        gk[p * 8 + 2 + h] = k.y;
        gk[p * 8 + 4 + h] = k.z;
        gk[p * 8 + 6 + h] = k.w;
    }
    load_w(wV, wc, ws);
    {
        float4 v = layer_and_measure(er, ei, wc, ws);
        gv[p * 8 + 0 + h] = v.x;
        gv[p * 8 + 2 + h] = v.y;
        gv[p * 8 + 4 + h] = v.z;
        gv[p * 8 + 6 + h] = v.w;
    }
}

// ---------------------------------------------------------------------------
// Kernel 2: split-K flash attention partials. R3's exact inner loop and block
// shape (TPB=64, 2 queries/thread, 2 keys per packed lane-pair), split across
// NSPLIT key halves for 2x warp parallelism. No epilogue -> low regs -> high
// register-limited occupancy. Raw exp2 softmax (scores in [-2,2]): partials
// combine exactly by summation.
// ---------------------------------------------------------------------------
#define ATTN_TPB   64
#define KEYS_HALF  (SS / NSPLIT)        // 1024 keys = 1024 packed float4

__global__ void __launch_bounds__(ATTN_TPB)
attn_kernel()
{
    __shared__ float4 sK[KEYS_HALF];
    __shared__ float4 sV[KEYS_HALF];

    const int b     = blockIdx.y;
    const int split = blockIdx.z;
    const int t     = threadIdx.x;
    const int qrow  = b * SS + blockIdx.x * (ATTN_TPB * 2) + t;

    // Stage this split's K/V half.
#pragma unroll
    for (int i = t; i < KEYS_HALF; i += ATTN_TPB) {
        sK[i] = g_Kp[b * SS + split * KEYS_HALF + i];
        sV[i] = g_Vp[b * SS + split * KEYS_HALF + i];
    }

    float4 qa = g_Q[qrow];
    float4 qb = g_Q[qrow + ATTN_TPB];

    const ull qa_x = pack2(qa.x, qa.x), qa_y = pack2(qa.y, qa.y);
    const ull qa_z = pack2(qa.z, qa.z), qa_w = pack2(qa.w, qa.w);
    const ull qb_x = pack2(qb.x, qb.x), qb_y = pack2(qb.y, qb.y);
    const ull qb_z = pack2(qb.z, qb.z), qb_w = pack2(qb.w, qb.w);

    ull den_a = 0, den_b = 0;
    ull aa0 = 0, aa1 = 0, aa2 = 0, aa3 = 0;
    ull ab0 = 0, ab1 = 0, ab2 = 0, ab3 = 0;

    __syncthreads();

    const ulonglong2* kk = (const ulonglong2*)sK;
    const ulonglong2* vv = (const ulonglong2*)sV;

#pragma unroll 4
    for (int p = 0; p < KEYS_HALF / 2; p++) {
        ulonglong2 ka = kk[2 * p];      // (kx pair, ky pair)
        ulonglong2 kb = kk[2 * p + 1];  // (kz pair, kw pair)

        ull sa = fma2(qa_x, ka.x, fma2(qa_y, ka.y, fma2(qa_z, kb.x, mul2(qa_w, kb.y))));
        ull sb = fma2(qb_x, ka.x, fma2(qb_y, ka.y, fma2(qb_z, kb.x, mul2(qb_w, kb.y))));

        float s0, s1;
        unpack2(sa, s0, s1);
        ull ea = pack2(fast_exp2(s0), fast_exp2(s1));
        unpack2(sb, s0, s1);
        ull eb = pack2(fast_exp2(s0), fast_exp2(s1));

        den_a = add2(den_a, ea);
        den_b = add2(den_b, eb);

        ulonglong2 va = vv[2 * p];
        ulonglong2 vb = vv[2 * p + 1];

        aa0 = fma2(ea, va.x, aa0);
        aa1 = fma2(ea, va.y, aa1);
        aa2 = fma2(ea, vb.x, aa2);
        aa3 = fma2(ea, vb.y, aa3);
        ab0 = fma2(eb, va.x, ab0);
        ab1 = fma2(eb, va.y, ab1);
        ab2 = fma2(eb, vb.x, ab2);
        ab3 = fma2(eb, vb.y, ab3);
    }

    const int base = split * NROWS;
    {
        float d0, d1, u0, u1;
        float4 num;
        unpack2(aa0, u0, u1); num.x = u0 + u1;
        unpack2(aa1, u0, u1); num.y = u0 + u1;
        unpack2(aa2, u0, u1); num.z = u0 + u1;
        unpack2(aa3, u0, u1); num.w = u0 + u1;
        unpack2(den_a, d0, d1);
        g_pnum[base + qrow] = num;
        g_pden[base + qrow] = d0 + d1;
    }
    {
        float d0, d1, u0, u1;
        float4 num;
        unpack2(ab0, u0, u1); num.x = u0 + u1;
        unpack2(ab1, u0, u1); num.y = u0 + u1;
        unpack2(ab2, u0, u1); num.z = u0 + u1;
        unpack2(ab3, u0, u1); num.w = u0 + u1;
        unpack2(den_b, d0, d1);
        g_pnum[base + qrow + ATTN_TPB] = num;
        g_pden[base + qrow + ATTN_TPB] = d0 + d1;
    }
}

// ---------------------------------------------------------------------------
// Kernel 3: combine split partials -> ctx -> circuit(weights_C) -> out
// ---------------------------------------------------------------------------
__global__ void out_kernel(const float* __restrict__ wC, float4* __restrict__ out)
{
    int idx = blockIdx.x * blockDim.x + threadIdx.x;
    if (idx >= NROWS) return;

    float4 n0 = g_pnum[idx];
    float4 n1 = g_pnum[NROWS + idx];
    float  d  = g_pden[idx] + g_pden[NROWS + idx];
    float inv = __fdividef(1.f, d);
    float4 ctx = make_float4((n0.x + n1.x) * inv, (n0.y + n1.y) * inv,
                             (n0.z + n1.z) * inv, (n0.w + n1.w) * inv);

    float er[16], ei[16];
    embed(ctx, er, ei);

    float wc[4], ws[4];
    load_w(wC, wc, ws);
    out[idx] = layer_and_measure(er, ei, wc, ws);
}

// ---------------------------------------------------------------------------

extern "C" void kernel_launch(void* const* d_in, const int* in_sizes, int n_in,
                              void* d_out, int out_size)
{
    const float4* x  = (const float4*)d_in[0];
    const float*  wQ = (const float*)d_in[1];
    const float*  wK = (const float*)d_in[2];
    const float*  wV = (const float*)d_in[3];
    const float*  wC = (const float*)d_in[4];

    qkv_kernel<<<NROWS / 128, 128>>>(x, wQ, wK, wV);

    dim3 grid(SS / (ATTN_TPB * 2), BB, NSPLIT);
    attn_kernel<<<grid, ATTN_TPB>>>();

    out_kernel<<<NROWS / 128, 128>>>(wC, (float4*)d_out);
}

// round 7
// speedup vs baseline: 1.7767x; 1.1343x over previous
#include <cuda_runtime.h>

#define BB 32
#define SS 2048
#define NROWS (BB * SS)
#define NSPLIT 4

// Scratch: __device__ globals (no allocation allowed in kernel_launch).
__device__ float4 g_Q[NROWS];            // pre-scaled by 0.5*log2(e)
// Pair-packed layouts: for key pair p (rows 2p, 2p+1):
//   g_Kp[2p]   = (k0.x, k1.x, k0.y, k1.y)
//   g_Kp[2p+1] = (k0.z, k1.z, k0.w, k1.w)
__device__ float4 g_Kp[NROWS];
__device__ float4 g_Vp[NROWS];
__device__ float4 g_pnum[NSPLIT * NROWS];  // partial sum(e*V)
__device__ float  g_pden[NSPLIT * NROWS];  // partial sum(e)

typedef unsigned long long ull;

// ---------------------------------------------------------------------------
// Packed f32x2 helpers (sm_103a FFMA2 path — ptxas won't auto-fuse from C++)
// ---------------------------------------------------------------------------
__device__ __forceinline__ ull pack2(float lo, float hi) {
    ull r; asm("mov.b64 %0, {%1, %2};" : "=l"(r) : "f"(lo), "f"(hi)); return r;
}
__device__ __forceinline__ void unpack2(ull v, float& lo, float& hi) {
    asm("mov.b64 {%0, %1}, %2;" : "=f"(lo), "=f"(hi) : "l"(v));
}
__device__ __forceinline__ ull fma2(ull a, ull b, ull c) {
    ull d; asm("fma.rn.f32x2 %0, %1, %2, %3;" : "=l"(d) : "l"(a), "l"(b), "l"(c)); return d;
}
__device__ __forceinline__ ull mul2(ull a, ull b) {
    ull d; asm("mul.rn.f32x2 %0, %1, %2;" : "=l"(d) : "l"(a), "l"(b)); return d;
}
__device__ __forceinline__ ull add2(ull a, ull b) {
    ull d; asm("add.rn.f32x2 %0, %1, %2;" : "=l"(d) : "l"(a), "l"(b)); return d;
}
__device__ __forceinline__ float fast_exp2(float x) {
    float y; asm("ex2.approx.ftz.f32 %0, %1;" : "=f"(y) : "f"(x)); return y;
}

// ---------------------------------------------------------------------------
// 16-dim statevector circuit: qubit q lives at bit (3-q). Fully unrolled;
// CNOTs are free register renames.
// ---------------------------------------------------------------------------
template <int Q>
__device__ __forceinline__ void rx_gate(float sr[16], float si[16], float c, float sn) {
    const int m = 1 << (3 - Q);
#pragma unroll
    for (int i = 0; i < 16; i++) {
        if (!(i & m)) {
            const int j = i | m;
            float a0r = sr[i], a0i = si[i];
            float a1r = sr[j], a1i = si[j];
            sr[i] = c * a0r + sn * a1i;
            si[i] = c * a0i - sn * a1r;
            sr[j] = c * a1r + sn * a0i;
            si[j] = c * a1i - sn * a0r;
        }
    }
}

template <int Q>
__device__ __forceinline__ void cnot_gate(float sr[16], float si[16]) {
    const int cm = 1 << (3 - Q);
    const int tm = 1 << (3 - ((Q + 1) & 3));
#pragma unroll
    for (int i = 0; i < 16; i++) {
        if ((i & cm) && !(i & tm)) {
            const int j = i | tm;
            float t;
            t = sr[i]; sr[i] = sr[j]; sr[j] = t;
            t = si[i]; si[i] = si[j]; si[j] = t;
        }
    }
}

__device__ __forceinline__ float4 layer_and_measure(
    const float er[16], const float ei[16],
    const float wc[4], const float ws[4])
{
    float sr[16], si[16];
#pragma unroll
    for (int i = 0; i < 16; i++) { sr[i] = er[i]; si[i] = ei[i]; }

    rx_gate<0>(sr, si, wc[0], ws[0]);
    rx_gate<1>(sr, si, wc[1], ws[1]);
    rx_gate<2>(sr, si, wc[2], ws[2]);
    rx_gate<3>(sr, si, wc[3], ws[3]);
    cnot_gate<0>(sr, si);
    cnot_gate<1>(sr, si);
    cnot_gate<2>(sr, si);
    cnot_gate<3>(sr, si);

    float e0 = 0.f, e1 = 0.f, e2 = 0.f, e3 = 0.f;
#pragma unroll
    for (int i = 0; i < 16; i++) {
        float p = sr[i] * sr[i] + si[i] * si[i];
        e0 += (i & 8) ? -p : p;
        e1 += (i & 4) ? -p : p;
        e2 += (i & 2) ? -p : p;
        e3 += (i & 1) ? -p : p;
    }
    return make_float4(e0, e1, e2, e3);
}

// MUFU-based sincos: half-angles are small (x ~ N(0,1)*0.5, ctx in [-0.5,0.5])
// so __sincosf accuracy is far inside the 1e-3 tolerance.
__device__ __forceinline__ void embed(float4 ang, float er[16], float ei[16]) {
#pragma unroll
    for (int i = 0; i < 16; i++) { er[i] = 0.f; ei[i] = 0.f; }
    er[0] = 1.f;
    float c, sn;
    __sincosf(ang.x * 0.5f, &sn, &c); rx_gate<0>(er, ei, c, sn);
    __sincosf(ang.y * 0.5f, &sn, &c); rx_gate<1>(er, ei, c, sn);
    __sincosf(ang.z * 0.5f, &sn, &c); rx_gate<2>(er, ei, c, sn);
    __sincosf(ang.w * 0.5f, &sn, &c); rx_gate<3>(er, ei, c, sn);
}

// Weights: uniform across threads; keep precise sincosf (range [0, pi]).
__device__ __forceinline__ void load_w(const float* __restrict__ w, float wc[4], float ws[4]) {
#pragma unroll
    for (int i = 0; i < 4; i++) sincosf(w[i] * 0.5f, &ws[i], &wc[i]);
}

// ---------------------------------------------------------------------------
// Kernel 1: x -> Q (row layout, pre-scaled), K, V (pair-packed layout).
// ---------------------------------------------------------------------------
__global__ void qkv_kernel(const float4* __restrict__ x,
                           const float* __restrict__ wQ,
                           const float* __restrict__ wK,
                           const float* __restrict__ wV)
{
    int idx = blockIdx.x * blockDim.x + threadIdx.x;
    if (idx >= NROWS) return;

    float er[16], ei[16];
    embed(x[idx], er, ei);

    float wc[4], ws[4];
    const float scale = 0.5f * 1.4426950408889634f;  // 1/sqrt(E) * log2(e)
    load_w(wQ, wc, ws);
    {
        float4 qv = layer_and_measure(er, ei, wc, ws);
        qv.x *= scale; qv.y *= scale; qv.z *= scale; qv.w *= scale;
        g_Q[idx] = qv;
    }

    const int p = idx >> 1;
    const int h = idx & 1;
    float* gk = (float*)g_Kp;
    float* gv = (float*)g_Vp;

    load_w(wK, wc, ws);
    {
        float4 k = layer_and_measure(er, ei, wc, ws);
        gk[p * 8 + 0 + h] = k.x;
        gk[p * 8 + 2 + h] = k.y;
        gk[p * 8 + 4 + h] = k.z;
        gk[p * 8 + 6 + h] = k.w;
    }
    load_w(wV, wc, ws);
    {
        float4 v = layer_and_measure(er, ei, wc, ws);
        gv[p * 8 + 0 + h] = v.x;
        gv[p * 8 + 2 + h] = v.y;
        gv[p * 8 + 4 + h] = v.z;
        gv[p * 8 + 6 + h] = v.w;
    }
}

// ---------------------------------------------------------------------------
// Kernel 2: split-K flash attention partials.
// QPT=2 queries/thread (keeps per-pair LDS traffic at the proven R3 level),
// 2 keys per packed f32x2 lane-pair, split-K=4 + TPB=128 for 4096 warps
// (~28/SM) to cover the ~50-cycle dot->ex2->acc dependency chain.
// Raw exp2 softmax (scores in [-2.9,2.9]): partials combine exactly by sum.
// ---------------------------------------------------------------------------
#define ATTN_TPB   128
#define KEYS_SPLIT (SS / NSPLIT)        // 512 keys = 512 packed float4

__global__ void __launch_bounds__(ATTN_TPB)
attn_kernel()
{
    __shared__ float4 sK[KEYS_SPLIT];
    __shared__ float4 sV[KEYS_SPLIT];

    const int b     = blockIdx.y;
    const int split = blockIdx.z;
    const int t     = threadIdx.x;
    const int qrow  = b * SS + blockIdx.x * (ATTN_TPB * 2) + t;

    // Stage this split's K/V slice.
#pragma unroll
    for (int i = t; i < KEYS_SPLIT; i += ATTN_TPB) {
        sK[i] = g_Kp[b * SS + split * KEYS_SPLIT + i];
        sV[i] = g_Vp[b * SS + split * KEYS_SPLIT + i];
    }

    float4 qa = g_Q[qrow];
    float4 qb = g_Q[qrow + ATTN_TPB];

    const ull qa_x = pack2(qa.x, qa.x), qa_y = pack2(qa.y, qa.y);
    const ull qa_z = pack2(qa.z, qa.z), qa_w = pack2(qa.w, qa.w);
    const ull qb_x = pack2(qb.x, qb.x), qb_y = pack2(qb.y, qb.y);
    const ull qb_z = pack2(qb.z, qb.z), qb_w = pack2(qb.w, qb.w);

    ull den_a = 0, den_b = 0;
    ull aa0 = 0, aa1 = 0, aa2 = 0, aa3 = 0;
    ull ab0 = 0, ab1 = 0, ab2 = 0, ab3 = 0;

    __syncthreads();

    const ulonglong2* kk = (const ulonglong2*)sK;
    const ulonglong2* vv = (const ulonglong2*)sV;

#pragma unroll 8
    for (int p = 0; p < KEYS_SPLIT / 2; p++) {
        ulonglong2 ka = kk[2 * p];      // (kx pair, ky pair)
        ulonglong2 kb = kk[2 * p + 1];  // (kz pair, kw pair)

        ull sa = fma2(qa_x, ka.x, fma2(qa_y, ka.y, fma2(qa_z, kb.x, mul2(qa_w, kb.y))));
        ull sb = fma2(qb_x, ka.x, fma2(qb_y, ka.y, fma2(qb_z, kb.x, mul2(qb_w, kb.y))));

        float s0, s1;
        unpack2(sa, s0, s1);
        ull ea = pack2(fast_exp2(s0), fast_exp2(s1));
        unpack2(sb, s0, s1);
        ull eb = pack2(fast_exp2(s0), fast_exp2(s1));

        den_a = add2(den_a, ea);
        den_b = add2(den_b, eb);

        ulonglong2 va = vv[2 * p];
        ulonglong2 vb = vv[2 * p + 1];

        aa0 = fma2(ea, va.x, aa0);
        aa1 = fma2(ea, va.y, aa1);
        aa2 = fma2(ea, vb.x, aa2);
        aa3 = fma2(ea, vb.y, aa3);
        ab0 = fma2(eb, va.x, ab0);
        ab1 = fma2(eb, va.y, ab1);
        ab2 = fma2(eb, vb.x, ab2);
        ab3 = fma2(eb, vb.y, ab3);
    }

    const int base = split * NROWS;
    {
        float d0, d1, u0, u1;
        float4 num;
        unpack2(aa0, u0, u1); num.x = u0 + u1;
        unpack2(aa1, u0, u1); num.y = u0 + u1;
        unpack2(aa2, u0, u1); num.z = u0 + u1;
        unpack2(aa3, u0, u1); num.w = u0 + u1;
        unpack2(den_a, d0, d1);
        g_pnum[base + qrow] = num;
        g_pden[base + qrow] = d0 + d1;
    }
    {
        float d0, d1, u0, u1;
        float4 num;
        unpack2(ab0, u0, u1); num.x = u0 + u1;
        unpack2(ab1, u0, u1); num.y = u0 + u1;
        unpack2(ab2, u0, u1); num.z = u0 + u1;
        unpack2(ab3, u0, u1); num.w = u0 + u1;
        unpack2(den_b, d0, d1);
        g_pnum[base + qrow + ATTN_TPB] = num;
        g_pden[base + qrow + ATTN_TPB] = d0 + d1;
    }
}

// ---------------------------------------------------------------------------
// Kernel 3: combine split partials -> ctx -> circuit(weights_C) -> out
// ---------------------------------------------------------------------------
__global__ void out_kernel(const float* __restrict__ wC, float4* __restrict__ out)
{
    int idx = blockIdx.x * blockDim.x + threadIdx.x;
    if (idx >= NROWS) return;

    float4 num = g_pnum[idx];
    float  den = g_pden[idx];
#pragma unroll
    for (int s = 1; s < NSPLIT; s++) {
        float4 n = g_pnum[s * NROWS + idx];
        num.x += n.x; num.y += n.y; num.z += n.z; num.w += n.w;
        den += g_pden[s * NROWS + idx];
    }
    float inv = __fdividef(1.f, den);
    float4 ctx = make_float4(num.x * inv, num.y * inv, num.z * inv, num.w * inv);

    float er[16], ei[16];
    embed(ctx, er, ei);

    float wc[4], ws[4];
    load_w(wC, wc, ws);
    out[idx] = layer_and_measure(er, ei, wc, ws);
}

// ---------------------------------------------------------------------------

extern "C" void kernel_launch(void* const* d_in, const int* in_sizes, int n_in,
                              void* d_out, int out_size)
{
    const float4* x  = (const float4*)d_in[0];
    const float*  wQ = (const float*)d_in[1];
    const float*  wK = (const float*)d_in[2];
    const float*  wV = (const float*)d_in[3];
    const float*  wC = (const float*)d_in[4];

    qkv_kernel<<<NROWS / 128, 128>>>(x, wQ, wK, wV);

    dim3 grid(SS / (ATTN_TPB * 2), BB, NSPLIT);
    attn_kernel<<<grid, ATTN_TPB>>>();

    out_kernel<<<NROWS / 128, 128>>>(wC, (float4*)d_out);
}

// round 8
// speedup vs baseline: 1.8455x; 1.0388x over previous
#include <cuda_runtime.h>

#define BB 32
#define SS 2048
#define NROWS (BB * SS)
#define NSPLIT 8

// Scratch: __device__ globals (no allocation allowed in kernel_launch).
__device__ float4 g_Q[NROWS];            // pre-scaled by 0.5*log2(e)
// Pair-packed layouts: for key pair p (rows 2p, 2p+1):
//   g_Kp[2p]   = (k0.x, k1.x, k0.y, k1.y)
//   g_Kp[2p+1] = (k0.z, k1.z, k0.w, k1.w)
__device__ float4 g_Kp[NROWS];
__device__ float4 g_Vp[NROWS];
__device__ float4 g_pnum[NSPLIT * NROWS];  // partial sum(e*V)
__device__ float  g_pden[NSPLIT * NROWS];  // partial sum(e)

typedef unsigned long long ull;

// ---------------------------------------------------------------------------
// Packed f32x2 helpers (sm_103a FFMA2 path — ptxas won't auto-fuse from C++)
// ---------------------------------------------------------------------------
__device__ __forceinline__ ull pack2(float lo, float hi) {
    ull r; asm("mov.b64 %0, {%1, %2};" : "=l"(r) : "f"(lo), "f"(hi)); return r;
}
__device__ __forceinline__ void unpack2(ull v, float& lo, float& hi) {
    asm("mov.b64 {%0, %1}, %2;" : "=f"(lo), "=f"(hi) : "l"(v));
}
__device__ __forceinline__ ull fma2(ull a, ull b, ull c) {
    ull d; asm("fma.rn.f32x2 %0, %1, %2, %3;" : "=l"(d) : "l"(a), "l"(b), "l"(c)); return d;
}
__device__ __forceinline__ ull mul2(ull a, ull b) {
    ull d; asm("mul.rn.f32x2 %0, %1, %2;" : "=l"(d) : "l"(a), "l"(b)); return d;
}
__device__ __forceinline__ ull add2(ull a, ull b) {
    ull d; asm("add.rn.f32x2 %0, %1, %2;" : "=l"(d) : "l"(a), "l"(b)); return d;
}
__device__ __forceinline__ float fast_exp2(float x) {
    float y; asm("ex2.approx.ftz.f32 %0, %1;" : "=f"(y) : "f"(x)); return y;
}

// ---------------------------------------------------------------------------
// 16-dim statevector circuit: qubit q lives at bit (3-q). Fully unrolled;
// CNOTs are free register renames.
// ---------------------------------------------------------------------------
template <int Q>
__device__ __forceinline__ void rx_gate(float sr[16], float si[16], float c, float sn) {
    const int m = 1 << (3 - Q);
#pragma unroll
    for (int i = 0; i < 16; i++) {
        if (!(i & m)) {
            const int j = i | m;
            float a0r = sr[i], a0i = si[i];
            float a1r = sr[j], a1i = si[j];
            sr[i] = c * a0r + sn * a1i;
            si[i] = c * a0i - sn * a1r;
            sr[j] = c * a1r + sn * a0i;
            si[j] = c * a1i - sn * a0r;
        }
    }
}

template <int Q>
__device__ __forceinline__ void cnot_gate(float sr[16], float si[16]) {
    const int cm = 1 << (3 - Q);
    const int tm = 1 << (3 - ((Q + 1) & 3));
#pragma unroll
    for (int i = 0; i < 16; i++) {
        if ((i & cm) && !(i & tm)) {
            const int j = i | tm;
            float t;
            t = sr[i]; sr[i] = sr[j]; sr[j] = t;
            t = si[i]; si[i] = si[j]; si[j] = t;
        }
    }
}

__device__ __forceinline__ float4 layer_and_measure(
    const float er[16], const float ei[16],
    const float wc[4], const float ws[4])
{
    float sr[16], si[16];
#pragma unroll
    for (int i = 0; i < 16; i++) { sr[i] = er[i]; si[i] = ei[i]; }

    rx_gate<0>(sr, si, wc[0], ws[0]);
    rx_gate<1>(sr, si, wc[1], ws[1]);
    rx_gate<2>(sr, si, wc[2], ws[2]);
    rx_gate<3>(sr, si, wc[3], ws[3]);
    cnot_gate<0>(sr, si);
    cnot_gate<1>(sr, si);
    cnot_gate<2>(sr, si);
    cnot_gate<3>(sr, si);

    float e0 = 0.f, e1 = 0.f, e2 = 0.f, e3 = 0.f;
#pragma unroll
    for (int i = 0; i < 16; i++) {
        float p = sr[i] * sr[i] + si[i] * si[i];
        e0 += (i & 8) ? -p : p;
        e1 += (i & 4) ? -p : p;
        e2 += (i & 2) ? -p : p;
        e3 += (i & 1) ? -p : p;
    }
    return make_float4(e0, e1, e2, e3);
}

// MUFU-based sincos: half-angles are small (x ~ N(0,1)*0.5, ctx in [-0.5,0.5])
// so __sincosf accuracy is far inside the 1e-3 tolerance.
__device__ __forceinline__ void embed(float4 ang, float er[16], float ei[16]) {
#pragma unroll
    for (int i = 0; i < 16; i++) { er[i] = 0.f; ei[i] = 0.f; }
    er[0] = 1.f;
    float c, sn;
    __sincosf(ang.x * 0.5f, &sn, &c); rx_gate<0>(er, ei, c, sn);
    __sincosf(ang.y * 0.5f, &sn, &c); rx_gate<1>(er, ei, c, sn);
    __sincosf(ang.z * 0.5f, &sn, &c); rx_gate<2>(er, ei, c, sn);
    __sincosf(ang.w * 0.5f, &sn, &c); rx_gate<3>(er, ei, c, sn);
}

// Weights: half-angles in [0, pi] — __sincosf abs error ~2^-21 there, far
// inside the 1e-3 tolerance, and removes the precise-sincosf polynomial.
__device__ __forceinline__ void load_w(const float* __restrict__ w, float wc[4], float ws[4]) {
#pragma unroll
    for (int i = 0; i < 4; i++) __sincosf(w[i] * 0.5f, &ws[i], &wc[i]);
}

// ---------------------------------------------------------------------------
// Kernel 1: x -> Q (row layout, pre-scaled), K, V (pair-packed layout).
// ---------------------------------------------------------------------------
__global__ void qkv_kernel(const float4* __restrict__ x,
                           const float* __restrict__ wQ,
                           const float* __restrict__ wK,
                           const float* __restrict__ wV)
{
    int idx = blockIdx.x * blockDim.x + threadIdx.x;
    if (idx >= NROWS) return;

    float er[16], ei[16];
    embed(x[idx], er, ei);

    float wc[4], ws[4];
    const float scale = 0.5f * 1.4426950408889634f;  // 1/sqrt(E) * log2(e)
    load_w(wQ, wc, ws);
    {
        float4 qv = layer_and_measure(er, ei, wc, ws);
        qv.x *= scale; qv.y *= scale; qv.z *= scale; qv.w *= scale;
        g_Q[idx] = qv;
    }

    const int p = idx >> 1;
    const int h = idx & 1;
    float* gk = (float*)g_Kp;
    float* gv = (float*)g_Vp;

    load_w(wK, wc, ws);
    {
        float4 k = layer_and_measure(er, ei, wc, ws);
        gk[p * 8 + 0 + h] = k.x;
        gk[p * 8 + 2 + h] = k.y;
        gk[p * 8 + 4 + h] = k.z;
        gk[p * 8 + 6 + h] = k.w;
    }
    load_w(wV, wc, ws);
    {
        float4 v = layer_and_measure(er, ei, wc, ws);
        gv[p * 8 + 0 + h] = v.x;
        gv[p * 8 + 2 + h] = v.y;
        gv[p * 8 + 4 + h] = v.z;
        gv[p * 8 + 6 + h] = v.w;
    }
}

// ---------------------------------------------------------------------------
// Kernel 2: split-K flash attention partials.
// QPT=2 queries/thread (keeps per-pair LDS traffic at the proven R3 level),
// 2 keys per packed f32x2 lane-pair, split-K=8 + TPB=128 for 8192 warps
// (~24 resident/SM) to cover the ~50-cycle dot->ex2->acc dependency chain.
// Raw exp2 softmax (scores in [-2.9,2.9]): partials combine exactly by sum.
// ---------------------------------------------------------------------------
#define ATTN_TPB   128
#define KEYS_SPLIT (SS / NSPLIT)        // 256 keys = 256 packed float4

__global__ void __launch_bounds__(ATTN_TPB)
attn_kernel()
{
    __shared__ float4 sK[KEYS_SPLIT];
    __shared__ float4 sV[KEYS_SPLIT];

    const int b     = blockIdx.y;
    const int split = blockIdx.z;
    const int t     = threadIdx.x;
    const int qrow  = b * SS + blockIdx.x * (ATTN_TPB * 2) + t;

    // Stage this split's K/V slice.
#pragma unroll
    for (int i = t; i < KEYS_SPLIT; i += ATTN_TPB) {
        sK[i] = g_Kp[b * SS + split * KEYS_SPLIT + i];
        sV[i] = g_Vp[b * SS + split * KEYS_SPLIT + i];
    }

    float4 qa = g_Q[qrow];
    float4 qb = g_Q[qrow + ATTN_TPB];

    const ull qa_x = pack2(qa.x, qa.x), qa_y = pack2(qa.y, qa.y);
    const ull qa_z = pack2(qa.z, qa.z), qa_w = pack2(qa.w, qa.w);
    const ull qb_x = pack2(qb.x, qb.x), qb_y = pack2(qb.y, qb.y);
    const ull qb_z = pack2(qb.z, qb.z), qb_w = pack2(qb.w, qb.w);

    ull den_a = 0, den_b = 0;
    ull aa0 = 0, aa1 = 0, aa2 = 0, aa3 = 0;
    ull ab0 = 0, ab1 = 0, ab2 = 0, ab3 = 0;

    __syncthreads();

    const ulonglong2* kk = (const ulonglong2*)sK;
    const ulonglong2* vv = (const ulonglong2*)sV;

#pragma unroll 8
    for (int p = 0; p < KEYS_SPLIT / 2; p++) {
        ulonglong2 ka = kk[2 * p];      // (kx pair, ky pair)
        ulonglong2 kb = kk[2 * p + 1];  // (kz pair, kw pair)

        ull sa = fma2(qa_x, ka.x, fma2(qa_y, ka.y, fma2(qa_z, kb.x, mul2(qa_w, kb.y))));
        ull sb = fma2(qb_x, ka.x, fma2(qb_y, ka.y, fma2(qb_z, kb.x, mul2(qb_w, kb.y))));

        float s0, s1;
        unpack2(sa, s0, s1);
        ull ea = pack2(fast_exp2(s0), fast_exp2(s1));
        unpack2(sb, s0, s1);
        ull eb = pack2(fast_exp2(s0), fast_exp2(s1));

        den_a = add2(den_a, ea);
        den_b = add2(den_b, eb);

        ulonglong2 va = vv[2 * p];
        ulonglong2 vb = vv[2 * p + 1];

        aa0 = fma2(ea, va.x, aa0);
        aa1 = fma2(ea, va.y, aa1);
        aa2 = fma2(ea, vb.x, aa2);
        aa3 = fma2(ea, vb.y, aa3);
        ab0 = fma2(eb, va.x, ab0);
        ab1 = fma2(eb, va.y, ab1);
        ab2 = fma2(eb, vb.x, ab2);
        ab3 = fma2(eb, vb.y, ab3);
    }

    const int base = split * NROWS;
    {
        float d0, d1, u0, u1;
        float4 num;
        unpack2(aa0, u0, u1); num.x = u0 + u1;
        unpack2(aa1, u0, u1); num.y = u0 + u1;
        unpack2(aa2, u0, u1); num.z = u0 + u1;
        unpack2(aa3, u0, u1); num.w = u0 + u1;
        unpack2(den_a, d0, d1);
        g_pnum[base + qrow] = num;
        g_pden[base + qrow] = d0 + d1;
    }
    {
        float d0, d1, u0, u1;
        float4 num;
        unpack2(ab0, u0, u1); num.x = u0 + u1;
        unpack2(ab1, u0, u1); num.y = u0 + u1;
        unpack2(ab2, u0, u1); num.z = u0 + u1;
        unpack2(ab3, u0, u1); num.w = u0 + u1;
        unpack2(den_b, d0, d1);
        g_pnum[base + qrow + ATTN_TPB] = num;
        g_pden[base + qrow + ATTN_TPB] = d0 + d1;
    }
}

// ---------------------------------------------------------------------------
// Kernel 3: combine split partials -> ctx -> circuit(weights_C) -> out
// ---------------------------------------------------------------------------
__global__ void out_kernel(const float* __restrict__ wC, float4* __restrict__ out)
{
    int idx = blockIdx.x * blockDim.x + threadIdx.x;
    if (idx >= NROWS) return;

    float4 num = g_pnum[idx];
    float  den = g_pden[idx];
#pragma unroll
    for (int s = 1; s < NSPLIT; s++) {
        float4 n = g_pnum[s * NROWS + idx];
        num.x += n.x; num.y += n.y; num.z += n.z; num.w += n.w;
        den += g_pden[s * NROWS + idx];
    }
    float inv = __fdividef(1.f, den);
    float4 ctx = make_float4(num.x * inv, num.y * inv, num.z * inv, num.w * inv);

    float er[16], ei[16];
    embed(ctx, er, ei);

    float wc[4], ws[4];
    load_w(wC, wc, ws);
    out[idx] = layer_and_measure(er, ei, wc, ws);
}

// ---------------------------------------------------------------------------

extern "C" void kernel_launch(void* const* d_in, const int* in_sizes, int n_in,
                              void* d_out, int out_size)
{
    const float4* x  = (const float4*)d_in[0];
    const float*  wQ = (const float*)d_in[1];
    const float*  wK = (const float*)d_in[2];
    const float*  wV = (const float*)d_in[3];
    const float*  wC = (const float*)d_in[4];

    qkv_kernel<<<NROWS / 128, 128>>>(x, wQ, wK, wV);

    dim3 grid(SS / (ATTN_TPB * 2), BB, NSPLIT);
    attn_kernel<<<grid, ATTN_TPB>>>();

    out_kernel<<<NROWS / 128, 128>>>(wC, (float4*)d_out);
}

// round 10
// speedup vs baseline: 1.9111x; 1.0356x over previous
#include <cuda_runtime.h>

#define BB 32
#define SS 2048
#define NROWS (BB * SS)
#define NSPLIT 16

// Scratch: __device__ globals (no allocation allowed in kernel_launch).
__device__ float4 g_Q[NROWS];            // pre-scaled by 0.5*log2(e)
// Pair-packed layouts: for key pair p (rows 2p, 2p+1):
//   g_Kp[2p]   = (k0.x, k1.x, k0.y, k1.y)
//   g_Kp[2p+1] = (k0.z, k1.z, k0.w, k1.w)
__device__ float4 g_Kp[NROWS];
__device__ float4 g_Vp[NROWS];
__device__ float4 g_pnum[NSPLIT * NROWS];  // partial sum(e*V)
__device__ float  g_pden[NSPLIT * NROWS];  // partial sum(e)

typedef unsigned long long ull;

// ---------------------------------------------------------------------------
// Packed f32x2 helpers (sm_103a FFMA2 path — ptxas won't auto-fuse from C++)
// ---------------------------------------------------------------------------
__device__ __forceinline__ ull pack2(float lo, float hi) {
    ull r; asm("mov.b64 %0, {%1, %2};" : "=l"(r) : "f"(lo), "f"(hi)); return r;
}
__device__ __forceinline__ void unpack2(ull v, float& lo, float& hi) {
    asm("mov.b64 {%0, %1}, %2;" : "=f"(lo), "=f"(hi) : "l"(v));
}
__device__ __forceinline__ ull fma2(ull a, ull b, ull c) {
    ull d; asm("fma.rn.f32x2 %0, %1, %2, %3;" : "=l"(d) : "l"(a), "l"(b), "l"(c)); return d;
}
__device__ __forceinline__ ull mul2(ull a, ull b) {
    ull d; asm("mul.rn.f32x2 %0, %1, %2;" : "=l"(d) : "l"(a), "l"(b)); return d;
}
__device__ __forceinline__ ull add2(ull a, ull b) {
    ull d; asm("add.rn.f32x2 %0, %1, %2;" : "=l"(d) : "l"(a), "l"(b)); return d;
}
__device__ __forceinline__ float fast_exp2(float x) {
    float y; asm("ex2.approx.ftz.f32 %0, %1;" : "=f"(y) : "f"(x)); return y;
}

// ---------------------------------------------------------------------------
// 16-dim statevector circuit: qubit q lives at bit (3-q). Fully unrolled;
// CNOTs are free register renames.
// ---------------------------------------------------------------------------
template <int Q>
__device__ __forceinline__ void rx_gate(float sr[16], float si[16], float c, float sn) {
    const int m = 1 << (3 - Q);
#pragma unroll
    for (int i = 0; i < 16; i++) {
        if (!(i & m)) {
            const int j = i | m;
            float a0r = sr[i], a0i = si[i];
            float a1r = sr[j], a1i = si[j];
            sr[i] = c * a0r + sn * a1i;
            si[i] = c * a0i - sn * a1r;
            sr[j] = c * a1r + sn * a0i;
            si[j] = c * a1i - sn * a0r;
        }
    }
}

template <int Q>
__device__ __forceinline__ void cnot_gate(float sr[16], float si[16]) {
    const int cm = 1 << (3 - Q);
    const int tm = 1 << (3 - ((Q + 1) & 3));
#pragma unroll
    for (int i = 0; i < 16; i++) {
        if ((i & cm) && !(i & tm)) {
            const int j = i | tm;
            float t;
            t = sr[i]; sr[i] = sr[j]; sr[j] = t;
            t = si[i]; si[i] = si[j]; si[j] = t;
        }
    }
}

__device__ __forceinline__ float4 measure(const float sr[16], const float si[16]) {
    float e0 = 0.f, e1 = 0.f, e2 = 0.f, e3 = 0.f;
#pragma unroll
    for (int i = 0; i < 16; i++) {
        float p = sr[i] * sr[i] + si[i] * si[i];
        e0 += (i & 8) ? -p : p;
        e1 += (i & 4) ? -p : p;
        e2 += (i & 2) ? -p : p;
        e3 += (i & 1) ? -p : p;
    }
    return make_float4(e0, e1, e2, e3);
}

__device__ __forceinline__ float4 layer_and_measure(
    const float er[16], const float ei[16],
    const float wc[4], const float ws[4])
{
    float sr[16], si[16];
#pragma unroll
    for (int i = 0; i < 16; i++) { sr[i] = er[i]; si[i] = ei[i]; }

    rx_gate<0>(sr, si, wc[0], ws[0]);
    rx_gate<1>(sr, si, wc[1], ws[1]);
    rx_gate<2>(sr, si, wc[2], ws[2]);
    rx_gate<3>(sr, si, wc[3], ws[3]);
    cnot_gate<0>(sr, si);
    cnot_gate<1>(sr, si);
    cnot_gate<2>(sr, si);
    cnot_gate<3>(sr, si);
    return measure(sr, si);
}

// MUFU-based sincos: half-angles are small (x ~ N(0,1)*0.5, ctx in [-0.5,0.5])
// so __sincosf accuracy is far inside the 1e-3 tolerance.
__device__ __forceinline__ void embed(float4 ang, float er[16], float ei[16]) {
#pragma unroll
    for (int i = 0; i < 16; i++) { er[i] = 0.f; ei[i] = 0.f; }
    er[0] = 1.f;
    float c, sn;
    __sincosf(ang.x * 0.5f, &sn, &c); rx_gate<0>(er, ei, c, sn);
    __sincosf(ang.y * 0.5f, &sn, &c); rx_gate<1>(er, ei, c, sn);
    __sincosf(ang.z * 0.5f, &sn, &c); rx_gate<2>(er, ei, c, sn);
    __sincosf(ang.w * 0.5f, &sn, &c); rx_gate<3>(er, ei, c, sn);
}

// Weights: half-angles in [0, pi] — __sincosf abs error far inside tolerance.
__device__ __forceinline__ void load_w(const float* __restrict__ w, float wc[4], float ws[4]) {
#pragma unroll
    for (int i = 0; i < 4; i++) __sincosf(w[i] * 0.5f, &ws[i], &wc[i]);
}

// ---------------------------------------------------------------------------
// Kernel 1: x -> Q (row layout, pre-scaled), K, V (pair-packed layout).
// Q/K/V circuits run gate-by-gate INTERLEAVED for 3x ILP: this kernel is
// grid-limited (65k threads = ~14 warps/SM max), so burning registers on
// three concurrent statevectors is free and covers the dependency chains.
// ---------------------------------------------------------------------------
__global__ void __launch_bounds__(128)
qkv_kernel(const float4* __restrict__ x,
           const float* __restrict__ wQ,
           const float* __restrict__ wK,
           const float* __restrict__ wV)
{
    int idx = blockIdx.x * blockDim.x + threadIdx.x;
    if (idx >= NROWS) return;

    float er[16], ei[16];
    embed(x[idx], er, ei);

    float qcc[4], qss[4], kcc[4], kss[4], vcc[4], vss[4];
    load_w(wQ, qcc, qss);
    load_w(wK, kcc, kss);
    load_w(wV, vcc, vss);

    float qr[16], qi[16], kr[16], ki[16], vr[16], vi[16];
#pragma unroll
    for (int i = 0; i < 16; i++) {
        qr[i] = er[i]; qi[i] = ei[i];
        kr[i] = er[i]; ki[i] = ei[i];
        vr[i] = er[i]; vi[i] = ei[i];
    }

    // Interleaved gates: three independent dependency chains in flight.
    rx_gate<0>(qr, qi, qcc[0], qss[0]);
    rx_gate<0>(kr, ki, kcc[0], kss[0]);
    rx_gate<0>(vr, vi, vcc[0], vss[0]);
    rx_gate<1>(qr, qi, qcc[1], qss[1]);
    rx_gate<1>(kr, ki, kcc[1], kss[1]);
    rx_gate<1>(vr, vi, vcc[1], vss[1]);
    rx_gate<2>(qr, qi, qcc[2], qss[2]);
    rx_gate<2>(kr, ki, kcc[2], kss[2]);
    rx_gate<2>(vr, vi, vcc[2], vss[2]);
    rx_gate<3>(qr, qi, qcc[3], qss[3]);
    rx_gate<3>(kr, ki, kcc[3], kss[3]);
    rx_gate<3>(vr, vi, vcc[3], vss[3]);
    cnot_gate<0>(qr, qi); cnot_gate<0>(kr, ki); cnot_gate<0>(vr, vi);
    cnot_gate<1>(qr, qi); cnot_gate<1>(kr, ki); cnot_gate<1>(vr, vi);
    cnot_gate<2>(qr, qi); cnot_gate<2>(kr, ki); cnot_gate<2>(vr, vi);
    cnot_gate<3>(qr, qi); cnot_gate<3>(kr, ki); cnot_gate<3>(vr, vi);

    const float scale = 0.5f * 1.4426950408889634f;  // 1/sqrt(E) * log2(e)
    {
        float4 qv = measure(qr, qi);
        qv.x *= scale; qv.y *= scale; qv.z *= scale; qv.w *= scale;
        g_Q[idx] = qv;
    }

    const int p = idx >> 1;
    const int h = idx & 1;
    float* gk = (float*)g_Kp;
    float* gv = (float*)g_Vp;
    {
        float4 k = measure(kr, ki);
        gk[p * 8 + 0 + h] = k.x;
        gk[p * 8 + 2 + h] = k.y;
        gk[p * 8 + 4 + h] = k.z;
        gk[p * 8 + 6 + h] = k.w;
    }
    {
        float4 v = measure(vr, vi);
        gv[p * 8 + 0 + h] = v.x;
        gv[p * 8 + 2 + h] = v.y;
        gv[p * 8 + 4 + h] = v.z;
        gv[p * 8 + 6 + h] = v.w;
    }
}

// ---------------------------------------------------------------------------
// Kernel 2: split-K flash attention partials.
// QPT=2 queries/thread, 2 keys per packed f32x2 lane-pair, split-K=16 for
// fine-grained tiles (4096 blocks) -> small fractional-wave tail.
// Raw exp2 softmax (scores in [-2.9,2.9]): partials combine exactly by sum.
// ---------------------------------------------------------------------------
#define ATTN_TPB   128
#define KEYS_SPLIT (SS / NSPLIT)        // 128 keys = 128 packed float4

__global__ void __launch_bounds__(ATTN_TPB)
attn_kernel()
{
    __shared__ float4 sK[KEYS_SPLIT];
    __shared__ float4 sV[KEYS_SPLIT];

    const int b     = blockIdx.y;
    const int split = blockIdx.z;
    const int t     = threadIdx.x;
    const int qrow  = b * SS + blockIdx.x * (ATTN_TPB * 2) + t;

    // Stage this split's K/V slice.
    if (t < KEYS_SPLIT) {
        sK[t] = g_Kp[b * SS + split * KEYS_SPLIT + t];
        sV[t] = g_Vp[b * SS + split * KEYS_SPLIT + t];
    }

    float4 qa = g_Q[qrow];
    float4 qb = g_Q[qrow + ATTN_TPB];

    const ull qa_x = pack2(qa.x, qa.x), qa_y = pack2(qa.y, qa.y);
    const ull qa_z = pack2(qa.z, qa.z), qa_w = pack2(qa.w, qa.w);
    const ull qb_x = pack2(qb.x, qb.x), qb_y = pack2(qb.y, qb.y);
    const ull qb_z = pack2(qb.z, qb.z), qb_w = pack2(qb.w, qb.w);

    ull den_a = 0, den_b = 0;
    ull aa0 = 0, aa1 = 0, aa2 = 0, aa3 = 0;
    ull ab0 = 0, ab1 = 0, ab2 = 0, ab3 = 0;

    __syncthreads();

    const ulonglong2* kk = (const ulonglong2*)sK;
    const ulonglong2* vv = (const ulonglong2*)sV;

#pragma unroll 8
    for (int p = 0; p < KEYS_SPLIT / 2; p++) {
        ulonglong2 ka = kk[2 * p];      // (kx pair, ky pair)
        ulonglong2 kb = kk[2 * p + 1];  // (kz pair, kw pair)

        ull sa = fma2(qa_x, ka.x, fma2(qa_y, ka.y, fma2(qa_z, kb.x, mul2(qa_w, kb.y))));
        ull sb = fma2(qb_x, ka.x, fma2(qb_y, ka.y, fma2(qb_z, kb.x, mul2(qb_w, kb.y))));

        float s0, s1;
        unpack2(sa, s0, s1);
        ull ea = pack2(fast_exp2(s0), fast_exp2(s1));
        unpack2(sb, s0, s1);
        ull eb = pack2(fast_exp2(s0), fast_exp2(s1));

        den_a = add2(den_a, ea);
        den_b = add2(den_b, eb);

        ulonglong2 va = vv[2 * p];
        ulonglong2 vb = vv[2 * p + 1];

        aa0 = fma2(ea, va.x, aa0);
        aa1 = fma2(ea, va.y, aa1);
        aa2 = fma2(ea, vb.x, aa2);
        aa3 = fma2(ea, vb.y, aa3);
        ab0 = fma2(eb, va.x, ab0);
        ab1 = fma2(eb, va.y, ab1);
        ab2 = fma2(eb, vb.x, ab2);
        ab3 = fma2(eb, vb.y, ab3);
    }

    const int base = split * NROWS;
    {
        float d0, d1, u0, u1;
        float4 num;
        unpack2(aa0, u0, u1); num.x = u0 + u1;
        unpack2(aa1, u0, u1); num.y = u0 + u1;
        unpack2(aa2, u0, u1); num.z = u0 + u1;
        unpack2(aa3, u0, u1); num.w = u0 + u1;
        unpack2(den_a, d0, d1);
        g_pnum[base + qrow] = num;
        g_pden[base + qrow] = d0 + d1;
    }
    {
        float d0, d1, u0, u1;
        float4 num;
        unpack2(ab0, u0, u1); num.x = u0 + u1;
        unpack2(ab1, u0, u1); num.y = u0 + u1;
        unpack2(ab2, u0, u1); num.z = u0 + u1;
        unpack2(ab3, u0, u1); num.w = u0 + u1;
        unpack2(den_b, d0, d1);
        g_pnum[base + qrow + ATTN_TPB] = num;
        g_pden[base + qrow + ATTN_TPB] = d0 + d1;
    }
}

// ---------------------------------------------------------------------------
// Kernel 3: combine split partials -> ctx -> circuit(weights_C) -> out
// ---------------------------------------------------------------------------
__global__ void out_kernel(const float* __restrict__ wC, float4* __restrict__ out)
{
    int idx = blockIdx.x * blockDim.x + threadIdx.x;
    if (idx >= NROWS) return;

    float4 num = g_pnum[idx];
    float  den = g_pden[idx];
#pragma unroll
    for (int s = 1; s < NSPLIT; s++) {
        float4 n = g_pnum[s * NROWS + idx];
        num.x += n.x; num.y += n.y; num.z += n.z; num.w += n.w;
        den += g_pden[s * NROWS + idx];
    }
    float inv = __fdividef(1.f, den);
    float4 ctx = make_float4(num.x * inv, num.y * inv, num.z * inv, num.w * inv);

    float er[16], ei[16];
    embed(ctx, er, ei);

    float wc[4], ws[4];
    load_w(wC, wc, ws);
    out[idx] = layer_and_measure(er, ei, wc, ws);
}

// ---------------------------------------------------------------------------

extern "C" void kernel_launch(void* const* d_in, const int* in_sizes, int n_in,
                              void* d_out, int out_size)
{
    const float4* x  = (const float4*)d_in[0];
    const float*  wQ = (const float*)d_in[1];
    const float*  wK = (const float*)d_in[2];
    const float*  wV = (const float*)d_in[3];
    const float*  wC = (const float*)d_in[4];

    qkv_kernel<<<NROWS / 128, 128>>>(x, wQ, wK, wV);

    dim3 grid(SS / (ATTN_TPB * 2), BB, NSPLIT);
    attn_kernel<<<grid, ATTN_TPB>>>();

    out_kernel<<<NROWS / 128, 128>>>(wC, (float4*)d_out);
}